// round 1
// baseline (speedup 1.0000x reference)
#include <cuda_runtime.h>
#include <math.h>

#define PATCH 7
#define PP 49

// Scratch: ping-pong activation buffers (N*D = 1024*256 = 262144 floats needed)
__device__ float g_buf0[1 << 19];
__device__ float g_buf1[1 << 19];

// ---------------------------------------------------------------------------
// Fused GEMM + bias (+ optional ReLU):  C[M,N] = A[M,K] @ W[K,N] + b
// BM=64, BN=64, BK=16, 256 threads (16x16), each thread computes 4x4.
// Assumes K % 16 == 0, N % 64 == 0 (D=256 here); guards M rows.
// ---------------------------------------------------------------------------
template <bool RELU>
__global__ void __launch_bounds__(256)
gemm_bias_kernel(const float* __restrict__ A, const float* __restrict__ W,
                 const float* __restrict__ bias, float* __restrict__ C,
                 int M, int N, int K) {
    __shared__ float As[64][17];
    __shared__ float Bs[16][68];

    const int tid = threadIdx.x;
    const int tx = tid & 15;          // 0..15 -> output cols
    const int ty = tid >> 4;          // 0..15 -> output rows
    const int block_m = blockIdx.y * 64;
    const int block_n = blockIdx.x * 64;

    // A-tile load mapping: 64x16 floats, one float4 per thread along K
    const int a_row = (tid * 4) >> 4;       // tid/4
    const int a_col = (tid * 4) & 15;       // (tid%4)*4
    // B-tile load mapping: 16x64 floats, one float4 per thread along N
    const int b_row = tid >> 4;             // tid/16
    const int b_col = (tid & 15) * 4;

    float acc[4][4];
#pragma unroll
    for (int i = 0; i < 4; i++)
#pragma unroll
        for (int j = 0; j < 4; j++) acc[i][j] = 0.f;

    for (int k0 = 0; k0 < K; k0 += 16) {
        // load A tile (guard M)
        float4 av = make_float4(0.f, 0.f, 0.f, 0.f);
        if (block_m + a_row < M)
            av = *reinterpret_cast<const float4*>(&A[(size_t)(block_m + a_row) * K + k0 + a_col]);
        As[a_row][a_col + 0] = av.x;
        As[a_row][a_col + 1] = av.y;
        As[a_row][a_col + 2] = av.z;
        As[a_row][a_col + 3] = av.w;

        float4 bv = *reinterpret_cast<const float4*>(&W[(size_t)(k0 + b_row) * N + block_n + b_col]);
        Bs[b_row][b_col + 0] = bv.x;
        Bs[b_row][b_col + 1] = bv.y;
        Bs[b_row][b_col + 2] = bv.z;
        Bs[b_row][b_col + 3] = bv.w;

        __syncthreads();

#pragma unroll
        for (int kk = 0; kk < 16; kk++) {
            float a[4], b[4];
#pragma unroll
            for (int i = 0; i < 4; i++) a[i] = As[ty * 4 + i][kk];
#pragma unroll
            for (int j = 0; j < 4; j++) b[j] = Bs[kk][tx * 4 + j];
#pragma unroll
            for (int i = 0; i < 4; i++)
#pragma unroll
                for (int j = 0; j < 4; j++) acc[i][j] = fmaf(a[i], b[j], acc[i][j]);
        }
        __syncthreads();
    }

    // epilogue: bias (+relu), float4 stores
    const int col = block_n + tx * 4;
    float4 bb = *reinterpret_cast<const float4*>(&bias[col]);
#pragma unroll
    for (int i = 0; i < 4; i++) {
        int row = block_m + ty * 4 + i;
        if (row >= M) break;
        float4 v;
        v.x = acc[i][0] + bb.x;
        v.y = acc[i][1] + bb.y;
        v.z = acc[i][2] + bb.z;
        v.w = acc[i][3] + bb.w;
        if (RELU) {
            v.x = fmaxf(v.x, 0.f);
            v.y = fmaxf(v.y, 0.f);
            v.z = fmaxf(v.z, 0.f);
            v.w = fmaxf(v.w, 0.f);
        }
        *reinterpret_cast<float4*>(&C[(size_t)row * N + col]) = v;
    }
}

// ---------------------------------------------------------------------------
// Patch gather + dot + indices.
// One block (256 threads = 8 warps) per query n.
// qe row cached in shared; each warp handles patch positions p = warp, warp+8, ...
// Each warp does a 256-float dot via 2x float4 per lane + shfl reduction.
// Output layout in d_out (float32):
//   [0, N*49)            logits, row-major (n, py, px)
//   [N*49, N*49*5)       indices as float, (n, py, px, {b,y,x,q})
// ---------------------------------------------------------------------------
__global__ void __launch_bounds__(256)
patch_kernel(const float* __restrict__ fm, const float* __restrict__ qe,
             const float* __restrict__ qpos, const int* __restrict__ shapes,
             float* __restrict__ out, int N, int Q, int D) {
    __shared__ float sq[256];
    const int n = blockIdx.x;
    if (n >= N) return;

    const int b = n / Q;
    const int q = n - b * Q;
    const int Hb = shapes[2 * b + 0];
    const int Wb = shapes[2 * b + 1];

    // center = int(pos[..., ::-1] * (H, W)) -- pos is (x, y) normalized
    const float posx = qpos[2 * n + 0];
    const float posy = qpos[2 * n + 1];
    const int cy = (int)(posy * (float)Hb);
    const int cx = (int)(posx * (float)Wb);

    for (int d = threadIdx.x; d < D; d += blockDim.x)
        sq[d] = qe[(size_t)n * D + d];
    __syncthreads();

    const int warp = threadIdx.x >> 5;
    const int lane = threadIdx.x & 31;
    const float4* sq4 = reinterpret_cast<const float4*>(sq);
    const float4 q0 = sq4[lane];
    const float4 q1 = sq4[lane + 32];

    float* out_logits = out;
    float* out_idx = out + (size_t)N * PP;

    for (int p = warp; p < PP; p += 8) {
        const int dy = p / PATCH - PATCH / 2;
        const int dx = p % PATCH - PATCH / 2;
        int y = cy + dy;
        int x = cx + dx;
        y = min(max(y, 0), Hb - 1);
        x = min(max(x, 0), Wb - 1);

        const size_t row_off = (((size_t)b * Hb + y) * Wb + x) * (size_t)D;
        const float4* row = reinterpret_cast<const float4*>(fm + row_off);

        const float4 f0 = row[lane];
        const float4 f1 = row[lane + 32];

        float s = f0.x * q0.x + f0.y * q0.y + f0.z * q0.z + f0.w * q0.w;
        s = fmaf(f1.x, q1.x, s);
        s = fmaf(f1.y, q1.y, s);
        s = fmaf(f1.z, q1.z, s);
        s = fmaf(f1.w, q1.w, s);

#pragma unroll
        for (int off = 16; off; off >>= 1)
            s += __shfl_xor_sync(0xFFFFFFFFu, s, off);

        if (lane == 0) {
            out_logits[(size_t)n * PP + p] = s;
            float4 iv = make_float4((float)b, (float)y, (float)x, (float)q);
            *reinterpret_cast<float4*>(&out_idx[((size_t)n * PP + p) * 4]) = iv;
        }
    }
}

extern "C" void kernel_launch(void* const* d_in, const int* in_sizes, int n_in,
                              void* d_out, int out_size) {
    const float* fm      = (const float*)d_in[0];
    const float* queries = (const float*)d_in[1];
    const float* qpos    = (const float*)d_in[2];
    // d_in[3]: query_batch_offsets (uniform Q assumed, per reference)
    const int*   shapes  = (const int*)d_in[4];
    const float* W0 = (const float*)d_in[5];
    const float* b0 = (const float*)d_in[6];
    const float* W1 = (const float*)d_in[7];
    const float* b1 = (const float*)d_in[8];
    const float* W2 = (const float*)d_in[9];
    const float* b2 = (const float*)d_in[10];
    const float* W3 = (const float*)d_in[11];
    const float* b3 = (const float*)d_in[12];

    const int B = in_sizes[3];               // query_batch_offsets length
    const int D = in_sizes[6];               // bias length
    const int N = in_sizes[1] / D;           // total queries
    const int Q = N / B;

    float* buf0;
    float* buf1;
    cudaGetSymbolAddress((void**)&buf0, g_buf0);
    cudaGetSymbolAddress((void**)&buf1, g_buf1);

    dim3 block(256);
    dim3 grid_gemm(D / 64, (N + 63) / 64);

    // MLP: 3x (Linear+ReLU) + final Linear
    gemm_bias_kernel<true ><<<grid_gemm, block>>>(queries, W0, b0, buf0, N, D, D);
    gemm_bias_kernel<true ><<<grid_gemm, block>>>(buf0,    W1, b1, buf1, N, D, D);
    gemm_bias_kernel<true ><<<grid_gemm, block>>>(buf1,    W2, b2, buf0, N, D, D);
    gemm_bias_kernel<false><<<grid_gemm, block>>>(buf0,    W3, b3, buf1, N, D, D);

    // Patch logits + COO indices
    patch_kernel<<<N, block>>>(fm, buf1, qpos, shapes, (float*)d_out, N, Q, D);
}

// round 4
// speedup vs baseline: 1.5374x; 1.5374x over previous
#include <cuda_runtime.h>
#include <math.h>

#define PATCH 7
#define PP 49

#define BM 32
#define BN 64
#define BK 32
#define APAD 4   // As row stride = BM + APAD = 36

// Scratch: ping-pong activation buffers (N*D = 1024*256 = 262144 floats needed)
__device__ float g_buf0[1 << 19];
__device__ float g_buf1[1 << 19];

// ---------------------------------------------------------------------------
// Fused GEMM + bias (+ optional ReLU):  C[M,N] = A[M,K] @ W[K,N] + b
// BM=32, BN=64, BK=32, 128 threads, each thread computes 4x4.
// A staged k-major in smem (As[k][row]) so compute reads are 2x LDS.128 per
// k-step. Register double-buffering of global tiles, one sync per K-tile.
// Assumes K % 32 == 0, N % 64 == 0 (D=256 here); guards M rows.
// ---------------------------------------------------------------------------
template <bool RELU>
__global__ void __launch_bounds__(128)
gemm_bias_kernel(const float* __restrict__ A, const float* __restrict__ W,
                 const float* __restrict__ bias, float* __restrict__ C,
                 int M, int N, int K) {
    __shared__ float As[2][BK][BM + APAD];   // k-major, padded
    __shared__ float Bs[2][BK][BN];

    const int tid = threadIdx.x;
    const int block_m = blockIdx.y * BM;
    const int block_n = blockIdx.x * BN;

    // A-tile global load mapping: 32 rows x 32 k. row = tid%32, k-offset = (tid/32)*8
    const int a_row = tid & 31;
    const int a_kg  = tid >> 5;             // 0..3
    const bool a_ok = (block_m + a_row) < M;

    // B-tile global load mapping: 32 k x 64 n. thread loads rows kr, kr+8, kr+16, kr+24
    const int b_kr = tid >> 4;              // 0..7
    const int b_c  = (tid & 15) * 4;

    // Compute mapping: 4 rows x 4 cols per thread
    const int tx = tid & 15;                // col group
    const int ty = tid >> 4;                // row group (0..7)

    float4 aR0, aR1;                        // 8 k-consecutive A values
    float4 bR[4];

    const size_t a_base = (size_t)(block_m + a_row) * K + a_kg * 8;
    const size_t w_base = (size_t)b_kr * N + block_n + b_c;
    const size_t w_step = (size_t)8 * N;

    // ---- prefetch tile 0 ----
    {
        if (a_ok) {
            aR0 = *reinterpret_cast<const float4*>(&A[a_base]);
            aR1 = *reinterpret_cast<const float4*>(&A[a_base + 4]);
        } else {
            aR0 = aR1 = make_float4(0.f, 0.f, 0.f, 0.f);
        }
#pragma unroll
        for (int i = 0; i < 4; i++)
            bR[i] = *reinterpret_cast<const float4*>(&W[w_base + i * w_step]);
    }
    // store tile 0
    {
        const float* av = &aR0.x;
#pragma unroll
        for (int j = 0; j < 4; j++) As[0][a_kg * 8 + j][a_row] = av[j];
        const float* av1 = &aR1.x;
#pragma unroll
        for (int j = 0; j < 4; j++) As[0][a_kg * 8 + 4 + j][a_row] = av1[j];
#pragma unroll
        for (int i = 0; i < 4; i++)
            *reinterpret_cast<float4*>(&Bs[0][b_kr + i * 8][b_c]) = bR[i];
    }
    __syncthreads();

    float acc[4][4];
#pragma unroll
    for (int i = 0; i < 4; i++)
#pragma unroll
        for (int j = 0; j < 4; j++) acc[i][j] = 0.f;

    const int nt = K / BK;
    int cur = 0;

    for (int t = 0; t < nt; t++) {
        // prefetch next tile into registers
        if (t + 1 < nt) {
            const size_t koff = (size_t)(t + 1) * BK;
            if (a_ok) {
                aR0 = *reinterpret_cast<const float4*>(&A[a_base + koff]);
                aR1 = *reinterpret_cast<const float4*>(&A[a_base + koff + 4]);
            }
#pragma unroll
            for (int i = 0; i < 4; i++)
                bR[i] = *reinterpret_cast<const float4*>(&W[w_base + koff * N + i * w_step]);
        }

        // compute on current buffer
#pragma unroll
        for (int kk = 0; kk < BK; kk++) {
            float4 a4 = *reinterpret_cast<const float4*>(&As[cur][kk][ty * 4]);
            float4 b4 = *reinterpret_cast<const float4*>(&Bs[cur][kk][tx * 4]);
            const float* ap = &a4.x;
            const float* bp = &b4.x;
#pragma unroll
            for (int i = 0; i < 4; i++)
#pragma unroll
                for (int j = 0; j < 4; j++)
                    acc[i][j] = fmaf(ap[i], bp[j], acc[i][j]);
        }

        // store next tile to the other buffer
        if (t + 1 < nt) {
            const int nxt = cur ^ 1;
            const float* av = &aR0.x;
#pragma unroll
            for (int j = 0; j < 4; j++) As[nxt][a_kg * 8 + j][a_row] = av[j];
            const float* av1 = &aR1.x;
#pragma unroll
            for (int j = 0; j < 4; j++) As[nxt][a_kg * 8 + 4 + j][a_row] = av1[j];
#pragma unroll
            for (int i = 0; i < 4; i++)
                *reinterpret_cast<float4*>(&Bs[nxt][b_kr + i * 8][b_c]) = bR[i];
        }
        __syncthreads();
        cur ^= 1;
    }

    // epilogue: bias (+relu), float4 stores
    const int col = block_n + tx * 4;
    float4 bb = *reinterpret_cast<const float4*>(&bias[col]);
#pragma unroll
    for (int i = 0; i < 4; i++) {
        int row = block_m + ty * 4 + i;
        if (row < M) {
            float4 v;
            v.x = acc[i][0] + bb.x;
            v.y = acc[i][1] + bb.y;
            v.z = acc[i][2] + bb.z;
            v.w = acc[i][3] + bb.w;
            if (RELU) {
                v.x = fmaxf(v.x, 0.f);
                v.y = fmaxf(v.y, 0.f);
                v.z = fmaxf(v.z, 0.f);
                v.w = fmaxf(v.w, 0.f);
            }
            *reinterpret_cast<float4*>(&C[(size_t)row * N + col]) = v;
        }
    }
}

// ---------------------------------------------------------------------------
// Patch gather + dot + indices.
// One block (256 threads = 8 warps) per query n.
// qe row cached in shared; each warp handles patch positions p = warp, warp+8.
// Output layout in d_out (float32):
//   [0, N*49)            logits, row-major (n, py, px)
//   [N*49, N*49*5)       indices as float, (n, py, px, {b,y,x,q})
// ---------------------------------------------------------------------------
__global__ void __launch_bounds__(256)
patch_kernel(const float* __restrict__ fm, const float* __restrict__ qe,
             const float* __restrict__ qpos, const int* __restrict__ shapes,
             float* __restrict__ out, int N, int Q, int D) {
    __shared__ float sq[256];
    const int n = blockIdx.x;
    if (n >= N) return;

    const int b = n / Q;
    const int q = n - b * Q;
    const int Hb = shapes[2 * b + 0];
    const int Wb = shapes[2 * b + 1];

    const float posx = qpos[2 * n + 0];
    const float posy = qpos[2 * n + 1];
    const int cy = (int)(posy * (float)Hb);
    const int cx = (int)(posx * (float)Wb);

    for (int d = threadIdx.x; d < D; d += blockDim.x)
        sq[d] = qe[(size_t)n * D + d];
    __syncthreads();

    const int warp = threadIdx.x >> 5;
    const int lane = threadIdx.x & 31;
    const float4* sq4 = reinterpret_cast<const float4*>(sq);
    const float4 q0 = sq4[lane];
    const float4 q1 = sq4[lane + 32];

    float* out_logits = out;
    float* out_idx = out + (size_t)N * PP;

    for (int p = warp; p < PP; p += 8) {
        const int dy = p / PATCH - PATCH / 2;
        const int dx = p % PATCH - PATCH / 2;
        int y = cy + dy;
        int x = cx + dx;
        y = min(max(y, 0), Hb - 1);
        x = min(max(x, 0), Wb - 1);

        const size_t row_off = (((size_t)b * Hb + y) * Wb + x) * (size_t)D;
        const float4* row = reinterpret_cast<const float4*>(fm + row_off);

        const float4 f0 = row[lane];
        const float4 f1 = row[lane + 32];

        float s = f0.x * q0.x + f0.y * q0.y + f0.z * q0.z + f0.w * q0.w;
        s = fmaf(f1.x, q1.x, s);
        s = fmaf(f1.y, q1.y, s);
        s = fmaf(f1.z, q1.z, s);
        s = fmaf(f1.w, q1.w, s);

#pragma unroll
        for (int off = 16; off; off >>= 1)
            s += __shfl_xor_sync(0xFFFFFFFFu, s, off);

        if (lane == 0) {
            out_logits[(size_t)n * PP + p] = s;
            float4 iv = make_float4((float)b, (float)y, (float)x, (float)q);
            *reinterpret_cast<float4*>(&out_idx[((size_t)n * PP + p) * 4]) = iv;
        }
    }
}

extern "C" void kernel_launch(void* const* d_in, const int* in_sizes, int n_in,
                              void* d_out, int out_size) {
    const float* fm      = (const float*)d_in[0];
    const float* queries = (const float*)d_in[1];
    const float* qpos    = (const float*)d_in[2];
    const int*   shapes  = (const int*)d_in[4];
    const float* W0 = (const float*)d_in[5];
    const float* b0 = (const float*)d_in[6];
    const float* W1 = (const float*)d_in[7];
    const float* b1 = (const float*)d_in[8];
    const float* W2 = (const float*)d_in[9];
    const float* b2 = (const float*)d_in[10];
    const float* W3 = (const float*)d_in[11];
    const float* b3 = (const float*)d_in[12];

    const int B = in_sizes[3];               // query_batch_offsets length
    const int D = in_sizes[6];               // bias length
    const int N = in_sizes[1] / D;           // total queries
    const int Q = N / B;

    float* buf0;
    float* buf1;
    cudaGetSymbolAddress((void**)&buf0, g_buf0);
    cudaGetSymbolAddress((void**)&buf1, g_buf1);

    dim3 block(128);
    dim3 grid_gemm(D / BN, (N + BM - 1) / BM);   // (4, 32) = 128 blocks

    gemm_bias_kernel<true ><<<grid_gemm, block>>>(queries, W0, b0, buf0, N, D, D);
    gemm_bias_kernel<true ><<<grid_gemm, block>>>(buf0,    W1, b1, buf1, N, D, D);
    gemm_bias_kernel<true ><<<grid_gemm, block>>>(buf1,    W2, b2, buf0, N, D, D);
    gemm_bias_kernel<false><<<grid_gemm, block>>>(buf0,    W3, b3, buf1, N, D, D);

    patch_kernel<<<N, 256>>>(fm, buf1, qpos, shapes, (float*)d_out, N, Q, D);
}